// round 1
// baseline (speedup 1.0000x reference)
#include <cuda_runtime.h>
#include <math.h>

#define NB 1024
#define NS 1024
#define DI 128
#define DS 64
#define KSEL 8

// Scratch (device globals: allocation-free per harness rules)
__device__ float g_H[(size_t)NB * NS * DS];       // 256 MB
__device__ float g_scores[(size_t)NB * NS];       // 4 MB

// ---- packed f32x2 helpers (FFMA2: 2x fp32 FMA throughput on sm_103a) ----
__device__ __forceinline__ unsigned long long fma2(unsigned long long a,
                                                   unsigned long long b,
                                                   unsigned long long c) {
    unsigned long long d;
    asm("fma.rn.f32x2 %0, %1, %2, %3;" : "=l"(d) : "l"(a), "l"(b), "l"(c));
    return d;
}
__device__ __forceinline__ unsigned long long dup2(float f) {
    unsigned int u = __float_as_uint(f);
    return ((unsigned long long)u << 32) | (unsigned long long)u;
}
__device__ __forceinline__ float lo2(unsigned long long v) { return __uint_as_float((unsigned int)v); }
__device__ __forceinline__ float hi2(unsigned long long v) { return __uint_as_float((unsigned int)(v >> 32)); }

// ============================================================================
// K1: fused MLP (two GEMMs) + per-row score. 64 rows per block.
//   H = relu(X@W1 + b1) @ W2 + b2          -> g_H
//   score = dot(H, mean_h(q)) / sqrt(64)   -> g_scores
// ============================================================================
static constexpr int BM = 64;
static constexpr int BK = 16;
static constexpr int XST = 66;  // padded stride (even -> 8B aligned pairs, conflict-friendly)

__global__ __launch_bounds__(256) void k1_mlp(
    const float* __restrict__ X, const float* __restrict__ W1,
    const float* __restrict__ b1, const float* __restrict__ W2,
    const float* __restrict__ b2, const float* __restrict__ q)
{
    __shared__ __align__(16) float XsT[BK][XST];   // X tile, transposed [k][row]
    __shared__ __align__(16) float W1t[BK][DS];    // W1 k-tile
    __shared__ __align__(16) float W2s[DS][DS];    // full W2
    __shared__ __align__(16) float TsT[DS][XST];   // hidden tile, transposed [k][row]
    __shared__ float qms[DS];

    const int tid = threadIdx.x;
    const int tx = tid & 15;        // 16 col-groups of 4
    const int ty = tid >> 4;        // 16 row-groups of 4
    const size_t row0 = (size_t)blockIdx.x * BM;

    // Preload full W2 (stays hot in L2 across blocks) and head-mean of q
    {
        const float4* src = (const float4*)W2;
        float4* dst = (float4*)&W2s[0][0];
        #pragma unroll
        for (int i = tid; i < DS * DS / 4; i += 256) dst[i] = src[i];
    }
    if (tid < DS) qms[tid] = 0.5f * (q[tid] + q[DS + tid]);

    unsigned long long acc0[4], acc1[4];
    #pragma unroll
    for (int j = 0; j < 4; j++) { acc0[j] = 0ULL; acc1[j] = 0ULL; }

    const int lr  = tid >> 2;   // 0..63 row to load
    const int lc4 = tid & 3;    // which float4 of the 16-wide k tile
    const int wkk = tid >> 4;   // W1 tile row
    const int wj4 = tid & 15;   // W1 tile col group

    // ---- GEMM1: T = relu(X @ W1 + b1), K = 128 in 8 tiles of 16 ----
    for (int k0 = 0; k0 < DI; k0 += BK) {
        float4 xv = *(const float4*)(X + (row0 + lr) * DI + k0 + lc4 * 4);
        float4 wv = *(const float4*)(W1 + (size_t)(k0 + wkk) * DS + wj4 * 4);
        __syncthreads();
        XsT[lc4 * 4 + 0][lr] = xv.x;
        XsT[lc4 * 4 + 1][lr] = xv.y;
        XsT[lc4 * 4 + 2][lr] = xv.z;
        XsT[lc4 * 4 + 3][lr] = xv.w;
        *(float4*)&W1t[wkk][wj4 * 4] = wv;
        __syncthreads();
        #pragma unroll
        for (int kk = 0; kk < BK; kk++) {
            unsigned long long a0 = *(const unsigned long long*)&XsT[kk][ty * 4];
            unsigned long long a1 = *(const unsigned long long*)&XsT[kk][ty * 4 + 2];
            float4 bv = *(const float4*)&W1t[kk][tx * 4];
            unsigned long long bb;
            bb = dup2(bv.x); acc0[0] = fma2(a0, bb, acc0[0]); acc1[0] = fma2(a1, bb, acc1[0]);
            bb = dup2(bv.y); acc0[1] = fma2(a0, bb, acc0[1]); acc1[1] = fma2(a1, bb, acc1[1]);
            bb = dup2(bv.z); acc0[2] = fma2(a0, bb, acc0[2]); acc1[2] = fma2(a1, bb, acc1[2]);
            bb = dup2(bv.w); acc0[3] = fma2(a0, bb, acc0[3]); acc1[3] = fma2(a1, bb, acc1[3]);
        }
    }

    // bias + relu -> TsT (transposed for phase-2 pair loads)
    {
        float4 b1v = *(const float4*)(b1 + tx * 4);
        float tt[4][4];
        #pragma unroll
        for (int j = 0; j < 4; j++) {
            float bj = (j == 0) ? b1v.x : (j == 1) ? b1v.y : (j == 2) ? b1v.z : b1v.w;
            tt[0][j] = fmaxf(lo2(acc0[j]) + bj, 0.0f);
            tt[1][j] = fmaxf(hi2(acc0[j]) + bj, 0.0f);
            tt[2][j] = fmaxf(lo2(acc1[j]) + bj, 0.0f);
            tt[3][j] = fmaxf(hi2(acc1[j]) + bj, 0.0f);
        }
        #pragma unroll
        for (int i = 0; i < 4; i++)
            #pragma unroll
            for (int j = 0; j < 4; j++)
                TsT[tx * 4 + j][ty * 4 + i] = tt[i][j];
    }
    __syncthreads();

    // ---- GEMM2: H = T @ W2 + b2, K = 64 ----
    #pragma unroll
    for (int j = 0; j < 4; j++) { acc0[j] = 0ULL; acc1[j] = 0ULL; }
    #pragma unroll 8
    for (int kk = 0; kk < DS; kk++) {
        unsigned long long a0 = *(const unsigned long long*)&TsT[kk][ty * 4];
        unsigned long long a1 = *(const unsigned long long*)&TsT[kk][ty * 4 + 2];
        float4 bv = *(const float4*)&W2s[kk][tx * 4];
        unsigned long long bb;
        bb = dup2(bv.x); acc0[0] = fma2(a0, bb, acc0[0]); acc1[0] = fma2(a1, bb, acc1[0]);
        bb = dup2(bv.y); acc0[1] = fma2(a0, bb, acc0[1]); acc1[1] = fma2(a1, bb, acc1[1]);
        bb = dup2(bv.z); acc0[2] = fma2(a0, bb, acc0[2]); acc1[2] = fma2(a1, bb, acc1[2]);
        bb = dup2(bv.w); acc0[3] = fma2(a0, bb, acc0[3]); acc1[3] = fma2(a1, bb, acc1[3]);
    }

    float4 b2v = *(const float4*)(b2 + tx * 4);
    float h[4][4];
    #pragma unroll
    for (int j = 0; j < 4; j++) {
        float bj = (j == 0) ? b2v.x : (j == 1) ? b2v.y : (j == 2) ? b2v.z : b2v.w;
        h[0][j] = lo2(acc0[j]) + bj;
        h[1][j] = hi2(acc0[j]) + bj;
        h[2][j] = lo2(acc1[j]) + bj;
        h[3][j] = hi2(acc1[j]) + bj;
    }

    // write H (coalesced float4)
    #pragma unroll
    for (int i = 0; i < 4; i++) {
        float4 hv = make_float4(h[i][0], h[i][1], h[i][2], h[i][3]);
        *(float4*)&g_H[(row0 + ty * 4 + i) * DS + tx * 4] = hv;
    }

    // per-row score: dot(H_row, qm) * (1/sqrt(64))
    float q0 = qms[tx * 4 + 0], q1 = qms[tx * 4 + 1], q2 = qms[tx * 4 + 2], q3 = qms[tx * 4 + 3];
    #pragma unroll
    for (int i = 0; i < 4; i++) {
        float v = h[i][0] * q0 + h[i][1] * q1 + h[i][2] * q2 + h[i][3] * q3;
        // butterfly-reduce across the 16 lanes sharing this ty (lanes split 0..15 / 16..31)
        #pragma unroll
        for (int m = 8; m > 0; m >>= 1) v += __shfl_xor_sync(0xffffffffu, v, m);
        if (tx == 0) g_scores[row0 + ty * 4 + i] = v * 0.125f;
    }
}

// ============================================================================
// K2: per-batch masked softmax + ctx + top-8 + gather. One block per batch.
// ============================================================================
__global__ __launch_bounds__(256) void k2_attn(
    const float* __restrict__ mask,
    float* __restrict__ out_sel, float* __restrict__ out_ctx,
    float* __restrict__ out_attn)
{
    __shared__ float sms[NS];     // masked scores
    __shared__ float ss[NS];      // safe scores for top-k (mutated)
    __shared__ float aw[NS];      // attention weights
    __shared__ float red[256];
    __shared__ int   redi[256];
    __shared__ float cpart[4][DS];
    __shared__ int   idxs[KSEL];

    const int t = threadIdx.x;
    const int b = blockIdx.x;
    const float* sc = g_scores + (size_t)b * NS;
    const float* mk = mask + (size_t)b * NS;

    // load + mask, track max
    float lmax = -INFINITY;
    #pragma unroll
    for (int u = 0; u < 4; u++) {
        int s = t + 256 * u;
        float v = sc[s];
        float m = (mk[s] > 0.5f) ? v : -INFINITY;
        sms[s] = m;
        lmax = fmaxf(lmax, m);
    }
    red[t] = lmax;
    __syncthreads();
    for (int off = 128; off > 0; off >>= 1) {
        if (t < off) red[t] = fmaxf(red[t], red[t + off]);
        __syncthreads();
    }
    const float mx = red[0];
    const bool allm = !(mx > -INFINITY);   // every slot masked
    __syncthreads();

    // exp + sum
    float lsum = 0.0f;
    #pragma unroll
    for (int u = 0; u < 4; u++) {
        int s = t + 256 * u;
        float m = sms[s];
        float e;
        if (allm)                   e = 1.0f;          // sm_in == 0 -> uniform
        else if (m == -INFINITY)    e = 0.0f;
        else                        e = expf(m - mx);
        aw[s] = e;
        lsum += e;
    }
    red[t] = lsum;
    __syncthreads();
    for (int off = 128; off > 0; off >>= 1) {
        if (t < off) red[t] += red[t + off];
        __syncthreads();
    }
    const float inv = 1.0f / red[0];
    __syncthreads();
    #pragma unroll
    for (int u = 0; u < 4; u++) {
        int s = t + 256 * u;
        float w = aw[s] * inv;
        aw[s] = w;
        out_attn[(size_t)b * NS + s] = w;
        ss[s] = allm ? 0.0f : sms[s];    // jax "safe_scores"
    }
    __syncthreads();

    // ctx[d] = sum_s aw[s] * H[b][s][d]
    const float* Hb = g_H + (size_t)b * NS * DS;
    {
        const int d = t & 63, part = t >> 6;
        float acc = 0.0f;
        const int s0 = part * 256;
        #pragma unroll 8
        for (int s = s0; s < s0 + 256; s++)
            acc += aw[s] * Hb[(size_t)s * DS + d];
        cpart[part][d] = acc;
    }
    __syncthreads();
    if (t < DS)
        out_ctx[(size_t)b * DS + t] =
            (cpart[0][t] + cpart[1][t]) + (cpart[2][t] + cpart[3][t]);

    // top-8 (descending; ties -> lower index, matching jax.lax.top_k)
    for (int it = 0; it < KSEL; it++) {
        float bv = -INFINITY; int bi = 0x7fffffff;
        #pragma unroll
        for (int u = 0; u < 4; u++) {
            int s = t + 256 * u;
            float v = ss[s];
            if (v > bv || (v == bv && s < bi)) { bv = v; bi = s; }
        }
        red[t] = bv; redi[t] = bi;
        __syncthreads();
        for (int off = 128; off > 0; off >>= 1) {
            if (t < off) {
                float v2 = red[t + off]; int i2 = redi[t + off];
                if (v2 > red[t] || (v2 == red[t] && i2 < redi[t])) { red[t] = v2; redi[t] = i2; }
            }
            __syncthreads();
        }
        if (t == 0) { idxs[it] = redi[0]; ss[redi[0]] = -INFINITY; }
        __syncthreads();
    }

    // gather sel[b][j][:] = H[b][idx_j][:]
    for (int e = t; e < KSEL * DS; e += 256) {
        int j = e >> 6, d = e & 63;
        out_sel[((size_t)b * KSEL + j) * DS + d] = Hb[(size_t)idxs[j] * DS + d];
    }
}

// ============================================================================
extern "C" void kernel_launch(void* const* d_in, const int* in_sizes, int n_in,
                              void* d_out, int out_size) {
    const float* X    = (const float*)d_in[0];   // slot_feats [B,S,DIN]
    const float* mask = (const float*)d_in[1];   // slot_mask  [B,S]
    const float* W1   = (const float*)d_in[2];   // [DIN,DSLOT]
    const float* b1   = (const float*)d_in[3];   // [DSLOT]
    const float* W2   = (const float*)d_in[4];   // [DSLOT,DSLOT]
    const float* b2   = (const float*)d_in[5];   // [DSLOT]
    const float* q    = (const float*)d_in[6];   // [NHEADS,DSLOT]
    // d_in[7] = k (constant 8; output layout already bakes it in)

    float* out      = (float*)d_out;
    float* out_sel  = out;                               // [B, 8, 64]
    float* out_ctx  = out + (size_t)NB * KSEL * DS;      // [B, 64]
    float* out_attn = out_ctx + (size_t)NB * DS;         // [B, S]

    k1_mlp<<<(NB * NS) / BM, 256>>>(X, W1, b1, W2, b2, q);
    k2_attn<<<NB, 256>>>(mask, out_sel, out_ctx, out_attn);
}